// round 10
// baseline (speedup 1.0000x reference)
#include <cuda_runtime.h>
#include <cuda_fp16.h>
#include <cstdint>

#define NOBJ 1024
#define TPB  256
#define JB   64        // actors per CTA chunk (16 chunks -> 1024 CTAs, 7 waves)
#define WST  72        // SMEM weight row stride (halfs): 144B -> conflict-free

// partial[m][jc][i][50]  (fully overwritten every launch by the 1024 CTAs)
__device__ float g_partial[8 * 16 * NOBJ * 50];

// ---------------------------------------------------------------------------
// mma.m16n8k16 row.col f32.f16.f16.f32
// A frag (4 b32): a0=(row g, k=2t4,2t4+1) a1=(g+8, same) a2=(g, +8) a3=(g+8, +8)
// B frag (2 b32): b0=(k=2t4,2t4+1, n=g)   b1=(k=+8, n=g)
// C frag (4 f32): c0=(g, n=2t4) c1=(g, 2t4+1) c2=(g+8, 2t4) c3=(g+8, 2t4+1)
// ---------------------------------------------------------------------------
__device__ __forceinline__ void mma16816(float c[4], const uint32_t a[4],
                                         uint32_t b0, uint32_t b1)
{
    asm("mma.sync.aligned.m16n8k16.row.col.f32.f16.f16.f32 "
        "{%0,%1,%2,%3}, {%4,%5,%6,%7}, {%8,%9}, {%0,%1,%2,%3};\n"
        : "+f"(c[0]), "+f"(c[1]), "+f"(c[2]), "+f"(c[3])
        : "r"(a[0]), "r"(a[1]), "r"(a[2]), "r"(a[3]), "r"(b0), "r"(b1));
}

__device__ __forceinline__ uint32_t pack2(float x, float y)
{
    half2 h = __floats2half2_rn(x, y);
    return *reinterpret_cast<uint32_t*>(&h);
}

// dithered pair: w_e = rn(w); w_o = rn(2w - w_e)  (error of w_o ~ -error(w_e))
__device__ __forceinline__ void dither_w(float v, half& we, half& wo)
{
    we = __float2half_rn(v);
    wo = __float2half_rn(2.f * v - __half2float(we));
}

__global__ void __launch_bounds__(TPB, 1)
pair_kernel(const float* __restrict__ obj0, const float* __restrict__ obj1,
            const float* __restrict__ prev0, const float* __restrict__ prev1,
            const float* __restrict__ gW0, const float* __restrict__ gb0,
            const float* __restrict__ gW1, const float* __restrict__ gb1,
            const float* __restrict__ gW2, const float* __restrict__ gb2)
{
    const int m  = blockIdx.x;   // module (actor class = m>>1, actee class = m&1)
    const int ib = blockIdx.y;   // i-block (128 actees)
    const int jc = blockIdx.z;   // j-chunk (64 actors, 16 chunks)
    const int t  = threadIdx.x;
    const int w  = t >> 5;
    const int lane = t & 31;
    const int t4 = lane & 3;
    const int g  = lane >> 2;

    const int ac = m >> 1;
    const float* actor = (ac == 0) ? obj0 : (ac == 1) ? obj1 : (ac == 2) ? prev0 : prev1;
    const float* actee = (m & 1) ? obj1 : obj0;

    // Transposed weights Wt[n][k] = W[k][n], k = 0..47 only (MMA part), with
    // even/odd dithered copies (fp16 rounding error flips sign by j-parity).
    // k = 48, 49 and the bias enter via exact fp32 tail FMAs (W1tail/W2tail).
    __shared__ half Wt1e[64 * WST], Wt1o[64 * WST];
    __shared__ half Wt2e[64 * WST], Wt2o[64 * WST];
    __shared__ float4 W1tail[56], W2tail[56];  // [col] = {w[48][col], w[49][col], bias[col], 0}
    __shared__ float alph[JB];

    for (int x = t; x < 64 * WST; x += TPB) {
        Wt1e[x] = __float2half(0.f);  Wt1o[x] = __float2half(0.f);
        Wt2e[x] = __float2half(0.f);  Wt2o[x] = __float2half(0.f);
    }
    __syncthreads();
    for (int x = t; x < 48 * 50; x += TPB) {
        int k = x / 50, n = x % 50;
        half we, wo;
        dither_w(gW1[m * 2500 + k * 50 + n], we, wo);
        Wt1e[n * WST + k] = we;  Wt1o[n * WST + k] = wo;
        dither_w(gW2[m * 2500 + k * 50 + n], we, wo);
        Wt2e[n * WST + k] = we;  Wt2o[n * WST + k] = wo;
    }
    if (t < 56) {
        bool real = t < 50;
        W1tail[t] = make_float4(real ? gW1[m * 2500 + 48 * 50 + t] : 0.f,
                                real ? gW1[m * 2500 + 49 * 50 + t] : 0.f,
                                real ? gb1[m * 50 + t] : 0.f, 0.f);
        W2tail[t] = make_float4(real ? gW2[m * 2500 + 48 * 50 + t] : 0.f,
                                real ? gW2[m * 2500 + 49 * 50 + t] : 0.f,
                                real ? gb2[m * 50 + t] : 0.f, 0.f);
    }
    if (t < JB) alph[t] = actor[jc * JB + t];

    // per-thread layer-1 constants at this thread's 12 fragment columns (k 0..47)
    float pc[12], qc[12], rc[12];
#pragma unroll
    for (int kt = 0; kt < 3; kt++)
#pragma unroll
        for (int s = 0; s < 4; s++) {
            int col = kt * 16 + 2 * t4 + ((s >> 1) << 3) + (s & 1);   // < 48
            int idx = kt * 4 + s;
            pc[idx] = gW0[m * 100 + col];        // W0[m][0][col]
            qc[idx] = gW0[m * 100 + 50 + col];   // W0[m][1][col]
            rc[idx] = gb0[m * 50 + col];
        }
    // tail columns 48, 49 (fp32, shared by all threads)
    const float p48 = gW0[m * 100 + 48], p49 = gW0[m * 100 + 49];
    const float q48 = gW0[m * 100 + 50 + 48], q49 = gW0[m * 100 + 50 + 49];
    const float r48 = gb0[m * 50 + 48], r49 = gb0[m * 50 + 49];

    const float betaA = actee[ib * 128 + w * 16 + g];
    const float betaB = actee[ib * 128 + w * 16 + g + 8];

    float Fr[28];
#pragma unroll
    for (int x = 0; x < 28; x++) Fr[x] = 0.f;

    __syncthreads();    // the ONLY barrier before the writeback

    for (int jj = 0; jj < JB; ++jj) {
        const float al = alph[jj];
        // parity-selected dithered weight set
        const half* __restrict__ W1 = (jj & 1) ? Wt1o : Wt1e;
        const half* __restrict__ W2 = (jj & 1) ? Wt2o : Wt2e;

        // ---- layer 1 (rank-1 collapse) -> A fragments (k 0..47) ----
        uint32_t A2h[3][4];
#pragma unroll
        for (int kt = 0; kt < 3; kt++) {
            const int b = kt * 4;
            float u0 = fmaf(al, pc[b + 0], rc[b + 0]);
            float u1 = fmaf(al, pc[b + 1], rc[b + 1]);
            float u2 = fmaf(al, pc[b + 2], rc[b + 2]);
            float u3 = fmaf(al, pc[b + 3], rc[b + 3]);
            float vA0 = fmaxf(fmaf(betaA, qc[b + 0], u0), 0.f);
            float vA1 = fmaxf(fmaf(betaA, qc[b + 1], u1), 0.f);
            float vA2 = fmaxf(fmaf(betaA, qc[b + 2], u2), 0.f);
            float vA3 = fmaxf(fmaf(betaA, qc[b + 3], u3), 0.f);
            float vB0 = fmaxf(fmaf(betaB, qc[b + 0], u0), 0.f);
            float vB1 = fmaxf(fmaf(betaB, qc[b + 1], u1), 0.f);
            float vB2 = fmaxf(fmaf(betaB, qc[b + 2], u2), 0.f);
            float vB3 = fmaxf(fmaf(betaB, qc[b + 3], u3), 0.f);
            A2h[kt][0] = pack2(vA0, vA1);
            A2h[kt][1] = pack2(vB0, vB1);
            A2h[kt][2] = pack2(vA2, vA3);
            A2h[kt][3] = pack2(vB2, vB3);
        }
        // layer-1 tail columns 48, 49 in fp32 (feed the rank-3 correction)
        const float u48 = fmaf(al, p48, r48), u49 = fmaf(al, p49, r49);
        const float h1A48 = fmaxf(fmaf(betaA, q48, u48), 0.f);
        const float h1A49 = fmaxf(fmaf(betaA, q49, u49), 0.f);
        const float h1B48 = fmaxf(fmaf(betaB, q48, u48), 0.f);
        const float h1B49 = fmaxf(fmaf(betaB, q49, u49), 0.f);

        // ---- layer 2: z2 = H1[:,0:48] @ W1d (MMA) + exact fp32 tail ----
        uint32_t A3h[3][4];
        uint32_t hgA = 0, hgB = 0;      // packed h2 cols (48,49), rows g / g+8
#pragma unroll
        for (int np = 0; np < 4; np++) {
            const int ntA = 2 * np, ntB = 2 * np + 1;   // ntB==7 disabled at np=3
            float cA0[4] = {0.f,0.f,0.f,0.f}, cA1[4] = {0.f,0.f,0.f,0.f};
            float cB0[4] = {0.f,0.f,0.f,0.f}, cB1[4] = {0.f,0.f,0.f,0.f};
            const int roA = (ntA * 8 + g) * WST + 2 * t4;
            const int roB = (ntB * 8 + g) * WST + 2 * t4;
#pragma unroll
            for (int kt = 0; kt < 3; kt++) {
                const half* phA = W1 + roA + kt * 16;
                uint32_t bA0 = *(const uint32_t*)phA;
                uint32_t bA1 = *(const uint32_t*)(phA + 8);
                mma16816((kt < 2) ? cA0 : cA1, A2h[kt], bA0, bA1);
                if (np < 3) {
                    const half* phB = W1 + roB + kt * 16;
                    uint32_t bB0 = *(const uint32_t*)phB;
                    uint32_t bB1 = *(const uint32_t*)(phB + 8);
                    mma16816((kt < 2) ? cB0 : cB1, A2h[kt], bB0, bB1);
                }
            }
            {   // tile ntA epilogue: rank-3 tail + bias + relu
                const int col0 = ntA * 8 + 2 * t4;
                float4 Ta = W1tail[col0], Tb = W1tail[col0 + 1];
                float z0 = cA0[0] + cA1[0] + h1A48 * Ta.x + h1A49 * Ta.y + Ta.z;
                float z1 = cA0[1] + cA1[1] + h1A48 * Tb.x + h1A49 * Tb.y + Tb.z;
                float z2 = cA0[2] + cA1[2] + h1B48 * Ta.x + h1B49 * Ta.y + Ta.z;
                float z3 = cA0[3] + cA1[3] + h1B48 * Tb.x + h1B49 * Tb.y + Tb.z;
                float v0 = fmaxf(z0, 0.f), v1 = fmaxf(z1, 0.f);
                float v2 = fmaxf(z2, 0.f), v3 = fmaxf(z3, 0.f);
                if (np < 3) {
                    const int kt2 = ntA >> 1;
                    A3h[kt2][0] = pack2(v0, v1);
                    A3h[kt2][1] = pack2(v2, v3);
                } else {     // ntA = 6: cols 48,49 live at t4==0 -> keep packed
                    hgA = pack2(v0, v1);
                    hgB = pack2(v2, v3);
                }
            }
            if (np < 3) {    // tile ntB epilogue
                const int col0 = ntB * 8 + 2 * t4;
                float4 Ta = W1tail[col0], Tb = W1tail[col0 + 1];
                float z0 = cB0[0] + cB1[0] + h1A48 * Ta.x + h1A49 * Ta.y + Ta.z;
                float z1 = cB0[1] + cB1[1] + h1A48 * Tb.x + h1A49 * Tb.y + Tb.z;
                float z2 = cB0[2] + cB1[2] + h1B48 * Ta.x + h1B49 * Ta.y + Ta.z;
                float z3 = cB0[3] + cB1[3] + h1B48 * Tb.x + h1B49 * Tb.y + Tb.z;
                const int kt2 = ntB >> 1;
                A3h[kt2][2] = pack2(fmaxf(z0, 0.f), fmaxf(z1, 0.f));
                A3h[kt2][3] = pack2(fmaxf(z2, 0.f), fmaxf(z3, 0.f));
            }
        }

        // broadcast h2 cols 48,49 (held by t4==0) to the whole quad
        {
            const int src = lane & ~3;
            uint32_t sA = __shfl_sync(0xffffffffu, hgA, src);
            uint32_t sB = __shfl_sync(0xffffffffu, hgB, src);
            half2 hA = *reinterpret_cast<half2*>(&sA);
            half2 hB = *reinterpret_cast<half2*>(&sB);
            float2 fA = __half22float2(hA);
            float2 fB = __half22float2(hB);
            const float h2A48 = fA.x, h2A49 = fA.y;   // rows g
            const float h2B48 = fB.x, h2B49 = fB.y;   // rows g+8

            // ---- layer 3: z3 = H2[:,0:48] @ W2d (MMA) + exact fp32 tail ----
#pragma unroll
            for (int np = 0; np < 4; np++) {
                const int ntA = 2 * np, ntB = 2 * np + 1;
                float cA0[4] = {0.f,0.f,0.f,0.f}, cA1[4] = {0.f,0.f,0.f,0.f};
                float cB0[4] = {0.f,0.f,0.f,0.f}, cB1[4] = {0.f,0.f,0.f,0.f};
                const int roA = (ntA * 8 + g) * WST + 2 * t4;
                const int roB = (ntB * 8 + g) * WST + 2 * t4;
#pragma unroll
                for (int kt = 0; kt < 3; kt++) {
                    const half* phA = W2 + roA + kt * 16;
                    uint32_t bA0 = *(const uint32_t*)phA;
                    uint32_t bA1 = *(const uint32_t*)(phA + 8);
                    mma16816((kt < 2) ? cA0 : cA1, A3h[kt], bA0, bA1);
                    if (np < 3) {
                        const half* phB = W2 + roB + kt * 16;
                        uint32_t bB0 = *(const uint32_t*)phB;
                        uint32_t bB1 = *(const uint32_t*)(phB + 8);
                        mma16816((kt < 2) ? cB0 : cB1, A3h[kt], bB0, bB1);
                    }
                }
                {
                    const int col0 = ntA * 8 + 2 * t4;
                    float4 Ta = W2tail[col0], Tb = W2tail[col0 + 1];
                    float z0 = cA0[0] + cA1[0] + h2A48 * Ta.x + h2A49 * Ta.y + Ta.z;
                    float z1 = cA0[1] + cA1[1] + h2A48 * Tb.x + h2A49 * Tb.y + Tb.z;
                    float z2 = cA0[2] + cA1[2] + h2B48 * Ta.x + h2B49 * Ta.y + Ta.z;
                    float z3 = cA0[3] + cA1[3] + h2B48 * Tb.x + h2B49 * Tb.y + Tb.z;
                    Fr[ntA * 4 + 0] += fmaxf(z0, 0.f);
                    Fr[ntA * 4 + 1] += fmaxf(z1, 0.f);
                    Fr[ntA * 4 + 2] += fmaxf(z2, 0.f);
                    Fr[ntA * 4 + 3] += fmaxf(z3, 0.f);
                }
                if (np < 3) {
                    const int col0 = ntB * 8 + 2 * t4;
                    float4 Ta = W2tail[col0], Tb = W2tail[col0 + 1];
                    float z0 = cB0[0] + cB1[0] + h2A48 * Ta.x + h2A49 * Ta.y + Ta.z;
                    float z1 = cB0[1] + cB1[1] + h2A48 * Tb.x + h2A49 * Tb.y + Tb.z;
                    float z2 = cB0[2] + cB1[2] + h2B48 * Ta.x + h2B49 * Ta.y + Ta.z;
                    float z3 = cB0[3] + cB1[3] + h2B48 * Tb.x + h2B49 * Tb.y + Tb.z;
                    Fr[ntB * 4 + 0] += fmaxf(z0, 0.f);
                    Fr[ntB * 4 + 1] += fmaxf(z1, 0.f);
                    Fr[ntB * 4 + 2] += fmaxf(z2, 0.f);
                    Fr[ntB * 4 + 3] += fmaxf(z3, 0.f);
                }
            }
        }
    }

    // ---- deterministic partial writeback (W3 folded post-sum in finalize) ----
    const int i0 = ib * 128 + w * 16 + g;
    const long base = (long)(m * 16 + jc) * NOBJ;
#pragma unroll
    for (int nt = 0; nt < 7; nt++) {
        const int col0 = nt * 8 + 2 * t4;
        if (col0 < 50) {
            g_partial[(base + i0) * 50 + col0]     = Fr[nt * 4 + 0];
            g_partial[(base + i0 + 8) * 50 + col0] = Fr[nt * 4 + 2];
        }
        if (col0 + 1 < 50) {
            g_partial[(base + i0) * 50 + col0 + 1]     = Fr[nt * 4 + 1];
            g_partial[(base + i0 + 8) * 50 + col0 + 1] = Fr[nt * 4 + 3];
        }
    }
}

// warp-per-(c,i) finalize: jc-reduce, fold W3, apply head MLP
__global__ void __launch_bounds__(256)
finalize_kernel(const float* __restrict__ gW3, const float* __restrict__ gb3,
                const float* __restrict__ aW0, const float* __restrict__ ab0,
                const float* __restrict__ aW1, const float* __restrict__ ab1,
                float* __restrict__ out)
{
    const int warp = blockIdx.x * (blockDim.x >> 5) + (threadIdx.x >> 5);
    const int lane = threadIdx.x & 31;

    if (warp >= 2048) return;
    const int c = warp >> 10;
    const int i = warp & 1023;

    float F[20];
#pragma unroll
    for (int o = 0; o < 20; o++) F[o] = 0.f;

    for (int idx = lane; idx < 200; idx += 32) {
        const int a = idx / 50, k = idx % 50;
        const int mm = a * 2 + c;
        const float* gp = g_partial + ((long)(mm * 16) * NOBJ + i) * 50 + k;
        float s = 0.f;
#pragma unroll
        for (int jcc = 0; jcc < 16; jcc++) s += gp[(long)jcc * NOBJ * 50];
        const float* w3 = gW3 + mm * 1000 + k * 20;
#pragma unroll
        for (int o = 0; o < 20; o++) F[o] = fmaf(s, w3[o], F[o]);
    }
#pragma unroll
    for (int off = 16; off; off >>= 1)
#pragma unroll
        for (int o = 0; o < 20; o++)
            F[o] += __shfl_xor_sync(0xffffffffu, F[o], off);
#pragma unroll
    for (int o = 0; o < 20; o++) {
        float b = gb3[(0 + c) * 20 + o] + gb3[(2 + c) * 20 + o]
                + gb3[(4 + c) * 20 + o] + gb3[(6 + c) * 20 + o];
        F[o] += 1024.f * b;
    }

    float p = 0.f;
    for (int l = lane; l < 50; l += 32) {
        float h = ab0[c * 50 + l];
#pragma unroll
        for (int o = 0; o < 20; o++)
            h = fmaf(F[o], aW0[c * 1000 + o * 50 + l], h);
        p = fmaf(fmaxf(h, 0.f), aW1[c * 50 + l], p);
    }
#pragma unroll
    for (int off = 16; off; off >>= 1)
        p += __shfl_xor_sync(0xffffffffu, p, off);
    if (lane == 0) out[c * 1024 + i] = p + ab1[c];
}

extern "C" void kernel_launch(void* const* d_in, const int* in_sizes, int n_in,
                              void* d_out, int out_size)
{
    const float* obj0  = (const float*)d_in[0];
    const float* obj1  = (const float*)d_in[1];
    const float* prev0 = (const float*)d_in[2];
    const float* prev1 = (const float*)d_in[3];
    const float* gW0   = (const float*)d_in[4];
    const float* gb0   = (const float*)d_in[5];
    const float* gW1   = (const float*)d_in[6];
    const float* gb1   = (const float*)d_in[7];
    const float* gW2   = (const float*)d_in[8];
    const float* gb2   = (const float*)d_in[9];
    const float* gW3   = (const float*)d_in[10];
    const float* gb3   = (const float*)d_in[11];
    const float* aW0   = (const float*)d_in[12];
    const float* ab0   = (const float*)d_in[13];
    const float* aW1   = (const float*)d_in[14];
    const float* ab1   = (const float*)d_in[15];

    dim3 grid(8, 8, 16);   // (module, i-block, j-chunk of 64) -> 1024 CTAs
    pair_kernel<<<grid, TPB>>>(obj0, obj1, prev0, prev1,
                               gW0, gb0, gW1, gb1, gW2, gb2);
    finalize_kernel<<<256, 256>>>(gW3, gb3, aW0, ab0, aW1, ab1, (float*)d_out);
}

// round 11
// speedup vs baseline: 1.1782x; 1.1782x over previous
#include <cuda_runtime.h>
#include <cuda_fp16.h>
#include <cstdint>

#define NOBJ 1024
#define TPB  256
#define JB   64        // actors per CTA chunk (16 chunks -> 1024 CTAs, 7 waves)
#define WST  80        // SMEM weight row stride (halfs): 160B == 32 mod 128
                       // -> conflict-free ld.shared.v2.u32 of B fragments

// partial[m][jc][i][50]  (fully overwritten every launch by the 1024 CTAs)
__device__ float g_partial[8 * 16 * NOBJ * 50];

// ---------------------------------------------------------------------------
// mma.m16n8k16 row.col f32.f16.f16.f32
// A frag (4 b32): a0=(row g, k=2t4,2t4+1) a1=(g+8, same) a2=(g, +8) a3=(g+8, +8)
// B frag (2 b32): b0=(k=2t4,2t4+1, n=g)   b1=(k=+8, n=g)
// C frag (4 f32): c0=(g, n=2t4) c1=(g, 2t4+1) c2=(g+8, 2t4) c3=(g+8, 2t4+1)
// ---------------------------------------------------------------------------
__device__ __forceinline__ void mma16816(float c[4], const uint32_t a[4],
                                         uint32_t b0, uint32_t b1)
{
    asm("mma.sync.aligned.m16n8k16.row.col.f32.f16.f16.f32 "
        "{%0,%1,%2,%3}, {%4,%5,%6,%7}, {%8,%9}, {%0,%1,%2,%3};\n"
        : "+f"(c[0]), "+f"(c[1]), "+f"(c[2]), "+f"(c[3])
        : "r"(a[0]), "r"(a[1]), "r"(a[2]), "r"(a[3]), "r"(b0), "r"(b1));
}

__device__ __forceinline__ uint32_t pack2(float x, float y)
{
    half2 h = __floats2half2_rn(x, y);
    return *reinterpret_cast<uint32_t*>(&h);
}

// dithered pair: w_e = rn(w); w_o = rn(2w - w_e)  (error of w_o ~ -error(w_e))
__device__ __forceinline__ void dither_w(float v, half& we, half& wo)
{
    we = __float2half_rn(v);
    wo = __float2half_rn(2.f * v - __half2float(we));
}

// k-interleaved SMEM slot for weight element at contraction index k (0..63):
// fragment thread t4 reads halfs {2t4, 2t4+1, 2t4+8, 2t4+9} of each 16-wide
// kt tile; store them contiguously so one v2 load fetches both b32 words.
__device__ __forceinline__ int kslot(int k)
{
    int kt = k >> 4, kk = k & 15;
    int t4s = (kk < 8) ? (kk >> 1) : ((kk - 8) >> 1);
    int c   = (kk < 8) ? (kk & 1)  : (2 + (kk & 1));
    return kt * 16 + t4s * 4 + c;
}

__global__ void __launch_bounds__(TPB, 1)
pair_kernel(const float* __restrict__ obj0, const float* __restrict__ obj1,
            const float* __restrict__ prev0, const float* __restrict__ prev1,
            const float* __restrict__ gW0, const float* __restrict__ gb0,
            const float* __restrict__ gW1, const float* __restrict__ gb1,
            const float* __restrict__ gW2, const float* __restrict__ gb2)
{
    const int m  = blockIdx.x;   // module (actor class = m>>1, actee class = m&1)
    const int ib = blockIdx.y;   // i-block (128 actees)
    const int jc = blockIdx.z;   // j-chunk (64 actors, 16 chunks)
    const int t  = threadIdx.x;
    const int w  = t >> 5;
    const int lane = t & 31;
    const int t4 = lane & 3;
    const int g  = lane >> 2;

    const int ac = m >> 1;
    const float* actor = (ac == 0) ? obj0 : (ac == 1) ? obj1 : (ac == 2) ? prev0 : prev1;
    const float* actee = (m & 1) ? obj1 : obj0;

    // Interleaved transposed weights; row k=50 carries the bias (fed by the
    // constant-1.0 col-50 of H). Even/odd dithered copies selected by PAIR
    // parity so a j-pair shares its B loads.
    __shared__ alignas(16) half Wt1e[64 * WST], Wt1o[64 * WST];
    __shared__ alignas(16) half Wt2e[64 * WST], Wt2o[64 * WST];
    __shared__ float alph[JB];

    for (int x = t; x < 64 * WST; x += TPB) {
        Wt1e[x] = __float2half(0.f);  Wt1o[x] = __float2half(0.f);
        Wt2e[x] = __float2half(0.f);  Wt2o[x] = __float2half(0.f);
    }
    __syncthreads();
    for (int x = t; x < 51 * 50; x += TPB) {
        int k = x / 50, n = x % 50;
        int s = n * WST + kslot(k);
        float w1 = (k < 50) ? gW1[m * 2500 + k * 50 + n] : gb1[m * 50 + n];
        float w2 = (k < 50) ? gW2[m * 2500 + k * 50 + n] : gb2[m * 50 + n];
        half we, wo;
        dither_w(w1, we, wo);  Wt1e[s] = we;  Wt1o[s] = wo;
        dither_w(w2, we, wo);  Wt2e[s] = we;  Wt2o[s] = wo;
    }
    if (t < JB) alph[t] = actor[jc * JB + t];

    // per-thread layer-1 constants at this thread's 16 fragment columns
    float pc[16], qc[16], rc[16];
#pragma unroll
    for (int kt = 0; kt < 4; kt++)
#pragma unroll
        for (int s = 0; s < 4; s++) {
            int col = kt * 16 + 2 * t4 + ((s >> 1) << 3) + (s & 1);
            int idx = kt * 4 + s;
            pc[idx] = (col < 50) ? gW0[m * 100 + col] : 0.f;        // W0[m][0][col]
            qc[idx] = (col < 50) ? gW0[m * 100 + 50 + col] : 0.f;   // W0[m][1][col]
            rc[idx] = (col < 50) ? gb0[m * 50 + col]
                                 : (col == 50 ? 1.f : 0.f);          // bias-feed col
        }
    const float betaA = actee[ib * 128 + w * 16 + g];
    const float betaB = actee[ib * 128 + w * 16 + g + 8];

    float Fr[28];
#pragma unroll
    for (int x = 0; x < 28; x++) Fr[x] = 0.f;

    // A3 kt=3 upper slots (k=56..63) always zero: nt=7 trimmed away
    uint32_t A3h[2][4][4];
    A3h[0][3][2] = A3h[0][3][3] = A3h[1][3][2] = A3h[1][3][3] = 0u;

    __syncthreads();    // the ONLY barrier before the writeback

    for (int jj = 0; jj < JB; jj += 2) {
        // pair-parity dithered weight set (both j's of the pair share B loads)
        const int par = (jj >> 1) & 1;
        const half* __restrict__ W1 = par ? Wt1o : Wt1e;
        const half* __restrict__ W2 = par ? Wt2o : Wt2e;

        // ---- layer 1 (rank-1 collapse) -> A fragments for both j's ----
        uint32_t A2h[2][4][4];
#pragma unroll
        for (int jx = 0; jx < 2; jx++) {
            const float al = alph[jj + jx];
#pragma unroll
            for (int kt = 0; kt < 4; kt++) {
                const int b = kt * 4;
                float u0 = fmaf(al, pc[b + 0], rc[b + 0]);
                float u1 = fmaf(al, pc[b + 1], rc[b + 1]);
                float u2 = fmaf(al, pc[b + 2], rc[b + 2]);
                float u3 = fmaf(al, pc[b + 3], rc[b + 3]);
                float vA0 = fmaxf(fmaf(betaA, qc[b + 0], u0), 0.f);
                float vA1 = fmaxf(fmaf(betaA, qc[b + 1], u1), 0.f);
                float vA2 = fmaxf(fmaf(betaA, qc[b + 2], u2), 0.f);
                float vA3 = fmaxf(fmaf(betaA, qc[b + 3], u3), 0.f);
                float vB0 = fmaxf(fmaf(betaB, qc[b + 0], u0), 0.f);
                float vB1 = fmaxf(fmaf(betaB, qc[b + 1], u1), 0.f);
                float vB2 = fmaxf(fmaf(betaB, qc[b + 2], u2), 0.f);
                float vB3 = fmaxf(fmaf(betaB, qc[b + 3], u3), 0.f);
                A2h[jx][kt][0] = pack2(vA0, vA1);
                A2h[jx][kt][1] = pack2(vB0, vB1);
                A2h[jx][kt][2] = pack2(vA2, vA3);
                A2h[jx][kt][3] = pack2(vB2, vB3);
            }
        }

        // ---- layer 2: z2 = H1 @ W1d (+b1 via col-50 feed) -> A3 (both j) ----
        // nt = 0..6 (cols 56..63 all-zero). One v2 load feeds 2 MMAs.
#pragma unroll
        for (int nt = 0; nt < 7; nt++) {
            float c0[2][4] = {{0.f,0.f,0.f,0.f},{0.f,0.f,0.f,0.f}};
            float c1[2][4] = {{0.f,0.f,0.f,0.f},{0.f,0.f,0.f,0.f}};
            const int ro = (nt * 8 + g) * WST + t4 * 4;
#pragma unroll
            for (int kt = 0; kt < 4; kt++) {
                uint2 bb = *(const uint2*)(W1 + ro + kt * 16);
                mma16816((kt < 2) ? c0[0] : c1[0], A2h[0][kt], bb.x, bb.y);
                mma16816((kt < 2) ? c0[1] : c1[1], A2h[1][kt], bb.x, bb.y);
            }
            const int col0 = nt * 8 + 2 * t4;
            const int kt2 = nt >> 1, s0 = (nt & 1) ? 2 : 0;
#pragma unroll
            for (int jx = 0; jx < 2; jx++) {
                float v0 = (col0 == 50) ? 1.f : fmaxf(c0[jx][0] + c1[jx][0], 0.f);
                float v1 = fmaxf(c0[jx][1] + c1[jx][1], 0.f);   // odd col, never 50
                float v2 = (col0 == 50) ? 1.f : fmaxf(c0[jx][2] + c1[jx][2], 0.f);
                float v3 = fmaxf(c0[jx][3] + c1[jx][3], 0.f);
                A3h[jx][kt2][s0]     = pack2(v0, v1);
                A3h[jx][kt2][s0 + 1] = pack2(v2, v3);
            }
        }

        // ---- layer 3: z3 = H2 @ W2d (+b2 via col-50 feed), relu, accum ----
#pragma unroll
        for (int nt = 0; nt < 7; nt++) {
            float c0[2][4] = {{0.f,0.f,0.f,0.f},{0.f,0.f,0.f,0.f}};
            float c1[2][4] = {{0.f,0.f,0.f,0.f},{0.f,0.f,0.f,0.f}};
            const int ro = (nt * 8 + g) * WST + t4 * 4;
#pragma unroll
            for (int kt = 0; kt < 4; kt++) {
                uint2 bb = *(const uint2*)(W2 + ro + kt * 16);
                mma16816((kt < 2) ? c0[0] : c1[0], A3h[0][kt], bb.x, bb.y);
                mma16816((kt < 2) ? c0[1] : c1[1], A3h[1][kt], bb.x, bb.y);
            }
#pragma unroll
            for (int jx = 0; jx < 2; jx++) {
                Fr[nt * 4 + 0] += fmaxf(c0[jx][0] + c1[jx][0], 0.f);
                Fr[nt * 4 + 1] += fmaxf(c0[jx][1] + c1[jx][1], 0.f);
                Fr[nt * 4 + 2] += fmaxf(c0[jx][2] + c1[jx][2], 0.f);
                Fr[nt * 4 + 3] += fmaxf(c0[jx][3] + c1[jx][3], 0.f);
            }
        }
    }

    // ---- deterministic partial writeback (W3 folded post-sum in finalize) ----
    const int i0 = ib * 128 + w * 16 + g;
    const long base = (long)(m * 16 + jc) * NOBJ;
#pragma unroll
    for (int nt = 0; nt < 7; nt++) {
        const int col0 = nt * 8 + 2 * t4;
        if (col0 < 50) {
            g_partial[(base + i0) * 50 + col0]     = Fr[nt * 4 + 0];
            g_partial[(base + i0 + 8) * 50 + col0] = Fr[nt * 4 + 2];
        }
        if (col0 + 1 < 50) {
            g_partial[(base + i0) * 50 + col0 + 1]     = Fr[nt * 4 + 1];
            g_partial[(base + i0 + 8) * 50 + col0 + 1] = Fr[nt * 4 + 3];
        }
    }
}

// warp-per-(c,i) finalize: jc-reduce, fold W3, apply head MLP
__global__ void __launch_bounds__(256)
finalize_kernel(const float* __restrict__ gW3, const float* __restrict__ gb3,
                const float* __restrict__ aW0, const float* __restrict__ ab0,
                const float* __restrict__ aW1, const float* __restrict__ ab1,
                float* __restrict__ out)
{
    const int warp = blockIdx.x * (blockDim.x >> 5) + (threadIdx.x >> 5);
    const int lane = threadIdx.x & 31;

    if (warp >= 2048) return;
    const int c = warp >> 10;
    const int i = warp & 1023;

    float F[20];
#pragma unroll
    for (int o = 0; o < 20; o++) F[o] = 0.f;

    for (int idx = lane; idx < 200; idx += 32) {
        const int a = idx / 50, k = idx % 50;
        const int mm = a * 2 + c;
        const float* gp = g_partial + ((long)(mm * 16) * NOBJ + i) * 50 + k;
        float s = 0.f;
#pragma unroll
        for (int jcc = 0; jcc < 16; jcc++) s += gp[(long)jcc * NOBJ * 50];
        const float* w3 = gW3 + mm * 1000 + k * 20;
#pragma unroll
        for (int o = 0; o < 20; o++) F[o] = fmaf(s, w3[o], F[o]);
    }
#pragma unroll
    for (int off = 16; off; off >>= 1)
#pragma unroll
        for (int o = 0; o < 20; o++)
            F[o] += __shfl_xor_sync(0xffffffffu, F[o], off);
#pragma unroll
    for (int o = 0; o < 20; o++) {
        float b = gb3[(0 + c) * 20 + o] + gb3[(2 + c) * 20 + o]
                + gb3[(4 + c) * 20 + o] + gb3[(6 + c) * 20 + o];
        F[o] += 1024.f * b;
    }

    float p = 0.f;
    for (int l = lane; l < 50; l += 32) {
        float h = ab0[c * 50 + l];
#pragma unroll
        for (int o = 0; o < 20; o++)
            h = fmaf(F[o], aW0[c * 1000 + o * 50 + l], h);
        p = fmaf(fmaxf(h, 0.f), aW1[c * 50 + l], p);
    }
#pragma unroll
    for (int off = 16; off; off >>= 1)
        p += __shfl_xor_sync(0xffffffffu, p, off);
    if (lane == 0) out[c * 1024 + i] = p + ab1[c];
}

extern "C" void kernel_launch(void* const* d_in, const int* in_sizes, int n_in,
                              void* d_out, int out_size)
{
    const float* obj0  = (const float*)d_in[0];
    const float* obj1  = (const float*)d_in[1];
    const float* prev0 = (const float*)d_in[2];
    const float* prev1 = (const float*)d_in[3];
    const float* gW0   = (const float*)d_in[4];
    const float* gb0   = (const float*)d_in[5];
    const float* gW1   = (const float*)d_in[6];
    const float* gb1   = (const float*)d_in[7];
    const float* gW2   = (const float*)d_in[8];
    const float* gb2   = (const float*)d_in[9];
    const float* gW3   = (const float*)d_in[10];
    const float* gb3   = (const float*)d_in[11];
    const float* aW0   = (const float*)d_in[12];
    const float* ab0   = (const float*)d_in[13];
    const float* aW1   = (const float*)d_in[14];
    const float* ab1   = (const float*)d_in[15];

    dim3 grid(8, 8, 16);   // (module, i-block, j-chunk of 64) -> 1024 CTAs
    pair_kernel<<<grid, TPB>>>(obj0, obj1, prev0, prev1,
                               gW0, gb0, gW1, gb1, gW2, gb2);
    finalize_kernel<<<256, 256>>>(gW3, gb3, aW0, ab0, aW1, ab1, (float*)d_out);
}